// round 6
// baseline (speedup 1.0000x reference)
#include <cuda_runtime.h>

#define BATCH   16
#define HW      1048576u
// score s in [0.75, 4.25] -> float bits in [0x3F400000, 0x40880000]
#define B1_MIN  259072u          // 0x3F400000 >> 12
#define B1_BINS 5249             // (0x40880 - 0x3F400) + 1
#define CAND_CAP 32768
#define GX 512
#define BT 256

__device__ unsigned g_hist[BATCH][B1_BINS];
__device__ unsigned g_np[BATCH];
__device__ unsigned g_cnt[BATCH];
__device__ uint2    g_cand[BATCH][CAND_CAP];   // x = key bits, y = idx in batch
__device__ unsigned g_T[BATCH];                // threshold level-1 bin (or ~0u)
__device__ unsigned g_k1[BATCH];               // quota inside threshold bin
__device__ unsigned g_ntr[BATCH];
__device__ unsigned g_V[BATCH];                // exact cutoff key
__device__ unsigned g_ic[BATCH];               // index cutoff among key==V
__device__ double   g_loss;

__device__ __forceinline__ unsigned score_key(float p, int m) {
    // bit-exact reproduction of the JAX f32 score
    float gt    = (float)m;
    float conf  = fmaxf(p, 1.0f - p);
    bool  corr  = (p > 0.5f) == (gt == 1.0f);
    bool  isc   = conf > 0.85f;
    float score = corr ? (isc ? 1.0f : 2.0f) : (isc ? 4.0f : 3.0f);
    float bonus = (conf - 0.5f) * 0.5f;      // exact in f32
    float s     = corr ? (score - bonus) : (score + bonus);
    return __float_as_uint(s);               // s > 0 => uint order == float order
}

__global__ void k_zero() {
    unsigned i = blockIdx.x * blockDim.x + threadIdx.x;
    unsigned stride = gridDim.x * blockDim.x;
    unsigned* h = &g_hist[0][0];
    for (unsigned j = i; j < BATCH * B1_BINS; j += stride) h[j] = 0u;
    if (i < BATCH) { g_np[i] = 0u; g_cnt[i] = 0u; }
    if (i == 0) g_loss = 0.0;
}

__global__ __launch_bounds__(BT) void k_hist(const float* __restrict__ pred,
                                             const int* __restrict__ mask) {
    __shared__ unsigned sh[B1_BINS];
    __shared__ unsigned scnt;
    int b = blockIdx.y;
    for (int i = threadIdx.x; i < B1_BINS; i += blockDim.x) sh[i] = 0u;
    if (threadIdx.x == 0) scnt = 0u;
    __syncthreads();

    const float* P = pred + (size_t)b * HW;
    const int*   M = mask + (size_t)b * HW;
    unsigned stride = blockDim.x * gridDim.x;
    unsigned localn = 0;
    for (unsigned i = blockIdx.x * blockDim.x + threadIdx.x; i < HW; i += stride) {
        int m = M[i];
        if (m != 2) {
            localn++;
            unsigned key = score_key(P[i], m);
            atomicAdd(&sh[(key >> 12) - B1_MIN], 1u);
        }
    }
    atomicAdd(&scnt, localn);
    __syncthreads();
    for (int i = threadIdx.x; i < B1_BINS; i += blockDim.x) {
        unsigned v = sh[i];
        if (v) atomicAdd(&g_hist[b][i], v);
    }
    if (threadIdx.x == 0) atomicAdd(&g_np[b], scnt);
}

__global__ __launch_bounds__(1024) void k_select() {
    __shared__ unsigned s[1024];
    int b = blockIdx.x;
    int t = threadIdx.x;
    const int PB = 6;                 // 1024*6 >= 5249
    unsigned local = 0;
    #pragma unroll
    for (int j = 0; j < PB; j++) {
        int pos = t * PB + j;
        if (pos < B1_BINS) local += g_hist[b][B1_BINS - 1 - pos];  // descending
    }
    s[t] = local; __syncthreads();
    for (int off = 1; off < 1024; off <<= 1) {
        unsigned v = (t >= off) ? s[t - off] : 0u;
        __syncthreads();
        s[t] += v;
        __syncthreads();
    }
    unsigned before = s[t] - local;
    unsigned np  = g_np[b];
    unsigned ntr = (unsigned)(int)((float)np * 0.5f);  // matches (f32(n)*0.5).astype(i32)
    if (t == 0) g_ntr[b] = ntr;
    if (ntr == 0) {
        if (t == 0) { g_T[b] = 0xFFFFFFFFu; g_k1[b] = 0u; }
        return;
    }
    if (before < ntr && before + local >= ntr) {
        unsigned acc = before;
        for (int j = 0; j < PB; j++) {
            int pos = t * PB + j;
            if (pos >= B1_BINS) break;
            int bin = B1_BINS - 1 - pos;
            unsigned h = g_hist[b][bin];
            if (acc + h >= ntr) { g_T[b] = (unsigned)bin; g_k1[b] = ntr - acc; break; }
            acc += h;
        }
    }
}

__global__ __launch_bounds__(BT) void k_collect(const float* __restrict__ pred,
                                                const int* __restrict__ mask) {
    int b = blockIdx.y;
    unsigned T = g_T[b];
    if (T == 0xFFFFFFFFu) return;
    const float* P = pred + (size_t)b * HW;
    const int*   M = mask + (size_t)b * HW;
    unsigned stride = blockDim.x * gridDim.x;
    for (unsigned i = blockIdx.x * blockDim.x + threadIdx.x; i < HW; i += stride) {
        int m = M[i];
        if (m != 2) {
            unsigned key = score_key(P[i], m);
            if (((key >> 12) - B1_MIN) == T) {
                unsigned pos = atomicAdd(&g_cnt[b], 1u);
                if (pos < CAND_CAP) g_cand[b][pos] = make_uint2(key, i);
            }
        }
    }
}

__global__ __launch_bounds__(256) void k_refine() {
    __shared__ unsigned h2[4096];
    __shared__ unsigned s[256];
    __shared__ unsigned eq[2048];
    __shared__ unsigned eqc;
    __shared__ unsigned shV, shKeq, shMeq;
    int b = blockIdx.x;
    int t = threadIdx.x;
    unsigned T = g_T[b];
    if (t == 0) {
        g_ic[b] = 0xFFFFFFFFu;                 // default: take all equals
        eqc = 0u; shV = 0xFFFFFFFFu; shKeq = 0u; shMeq = 0u;
        if (T != 0xFFFFFFFFu) g_V[b] = (T + B1_MIN) << 12;  // fallback (overwritten below)
        else                  g_V[b] = 0xFFFFFFFFu;         // select nothing
    }
    __syncthreads();
    if (T == 0xFFFFFFFFu) return;

    unsigned k1 = g_k1[b];
    unsigned nc = min(g_cnt[b], (unsigned)CAND_CAP);
    for (int i = t; i < 4096; i += 256) h2[i] = 0u;
    __syncthreads();
    for (unsigned i = t; i < nc; i += 256)
        atomicAdd(&h2[g_cand[b][i].x & 0xFFFu], 1u);
    __syncthreads();

    const int PB = 16;
    unsigned local = 0;
    #pragma unroll
    for (int j = 0; j < PB; j++) local += h2[4095 - (t * PB + j)];
    s[t] = local; __syncthreads();
    for (int off = 1; off < 256; off <<= 1) {
        unsigned v = (t >= off) ? s[t - off] : 0u;
        __syncthreads();
        s[t] += v;
        __syncthreads();
    }
    unsigned before = s[t] - local;
    if (before < k1 && before + local >= k1) {
        unsigned acc = before;
        for (int j = 0; j < PB; j++) {
            int v = 4095 - (t * PB + j);
            unsigned h = h2[v];
            if (acc + h >= k1) {
                unsigned V = ((T + B1_MIN) << 12) | (unsigned)v;
                shV = V; shKeq = k1 - acc; shMeq = h;
                g_V[b] = V;
                break;
            }
            acc += h;
        }
    }
    __syncthreads();
    unsigned V = shV, keq = shKeq, meq = shMeq;
    if (V == 0xFFFFFFFFu) return;            // degenerate fallback only
    if (keq == meq) return;                  // all equal-key elements selected

    for (unsigned i = t; i < nc; i += 256) {
        if (g_cand[b][i].x == V) {
            unsigned p = atomicAdd(&eqc, 1u);
            if (p < 2048u) eq[p] = g_cand[b][i].y;
        }
    }
    __syncthreads();
    unsigned m = min(eqc, 2048u);
    if (keq < m) {
        // find index with rank == keq (indices are distinct)
        for (unsigned i = t; i < m; i += 256) {
            unsigned x = eq[i], r = 0;
            for (unsigned j = 0; j < m; j++) r += (eq[j] < x) ? 1u : 0u;
            if (r == keq) g_ic[b] = x;       // select idx < g_ic
        }
    }
}

__global__ __launch_bounds__(BT) void k_final(const float* __restrict__ pred,
                                              const int* __restrict__ mask,
                                              float* __restrict__ out) {
    int b = blockIdx.y;
    unsigned V  = g_V[b];
    unsigned ic = g_ic[b];
    const float* P = pred + (size_t)b * HW;
    const int*   M = mask + (size_t)b * HW;
    float* outT = out + 1 + (size_t)b * HW;
    float* outH = out + 1 + (size_t)BATCH * HW + (size_t)b * HW;

    unsigned stride = blockDim.x * gridDim.x;
    double acc = 0.0;
    for (unsigned i = blockIdx.x * blockDim.x + threadIdx.x; i < HW; i += stride) {
        int   m = M[i];
        float p = P[i];
        bool ann = (m != 2);
        bool train = false;
        if (ann) {
            unsigned key = score_key(p, m);
            train = (key > V) || (key == V && i < ic);
        }
        bool hold = ann && !train;
        outT[i] = train ? 1.0f : 0.0f;
        outH[i] = hold  ? 1.0f : 0.0f;
        if (train) {
            float pc = fminf(fmaxf(p, 1e-7f), 1.0f - 1e-7f);
            float bce = (m == 1) ? -logf(pc) : -logf(1.0f - pc);
            acc += (double)bce;
        }
    }
    // warp + block reduce, one double atomic per block
    #pragma unroll
    for (int off = 16; off; off >>= 1)
        acc += __shfl_down_sync(0xFFFFFFFFu, acc, off);
    __shared__ double w[BT / 32];
    int lane = threadIdx.x & 31, warp = threadIdx.x >> 5;
    if (lane == 0) w[warp] = acc;
    __syncthreads();
    if (threadIdx.x == 0) {
        double s2 = 0.0;
        #pragma unroll
        for (int i = 0; i < BT / 32; i++) s2 += w[i];
        atomicAdd(&g_loss, s2);
    }
}

__global__ void k_fin(float* __restrict__ out) {
    if (threadIdx.x == 0 && blockIdx.x == 0) {
        unsigned tot = 0;
        #pragma unroll
        for (int b = 0; b < BATCH; b++) tot += g_ntr[b];
        out[0] = (float)g_loss / ((float)tot + 1e-7f);
    }
}

extern "C" void kernel_launch(void* const* d_in, const int* in_sizes, int n_in,
                              void* d_out, int out_size) {
    const float* pred = (const float*)d_in[0];
    const int*   mask = (const int*)d_in[1];
    float* out = (float*)d_out;
    dim3 grid(GX, BATCH);
    k_zero<<<330, 256>>>();
    k_hist<<<grid, BT>>>(pred, mask);
    k_select<<<BATCH, 1024>>>();
    k_collect<<<grid, BT>>>(pred, mask);
    k_refine<<<BATCH, 256>>>();
    k_final<<<grid, BT>>>(pred, mask, out);
    k_fin<<<1, 32>>>(out);
}

// round 8
// speedup vs baseline: 1.7273x; 1.7273x over previous
#include <cuda_runtime.h>

#define BATCH   16
#define HW      1048576u
#define HW4     262144u          // HW / 4
// score s in [0.75, 4.25] -> float bits in [0x3F400000, 0x40880000]
#define B1_MIN  259072u          // 0x3F400000 >> 12
#define B1_BINS 5249             // (0x40880 - 0x3F400) + 1
#define CAND_CAP 32768
#define BT  256
#define GXH 64                   // hist blocks per batch
#define GXC 128                  // collect blocks per batch
#define GXF 128                  // final blocks per batch

__device__ unsigned g_hist[BATCH][B1_BINS];
__device__ unsigned g_np[BATCH];
__device__ unsigned g_cnt[BATCH];
__device__ uint2    g_cand[BATCH][CAND_CAP];   // x = key bits, y = idx in batch
__device__ unsigned g_T[BATCH];                // threshold level-1 bin (or ~0u)
__device__ unsigned g_k1[BATCH];               // quota inside threshold bin
__device__ unsigned g_ntr[BATCH];
__device__ unsigned g_V[BATCH];                // exact cutoff key
__device__ unsigned g_ic[BATCH];               // index cutoff among key==V
__device__ double   g_loss;

__device__ __forceinline__ unsigned score_key(float p, int m) {
    // bit-exact reproduction of the JAX f32 score
    float gt    = (float)m;
    float conf  = fmaxf(p, 1.0f - p);
    bool  corr  = (p > 0.5f) == (gt == 1.0f);
    bool  isc   = conf > 0.85f;
    float score = corr ? (isc ? 1.0f : 2.0f) : (isc ? 4.0f : 3.0f);
    float bonus = (conf - 0.5f) * 0.5f;      // exact in f32
    float s     = corr ? (score - bonus) : (score + bonus);
    return __float_as_uint(s);               // s > 0 => uint order == float order
}

__global__ void k_zero() {
    unsigned i = blockIdx.x * blockDim.x + threadIdx.x;
    unsigned stride = gridDim.x * blockDim.x;
    unsigned* h = &g_hist[0][0];
    for (unsigned j = i; j < BATCH * B1_BINS; j += stride) h[j] = 0u;
    if (i < BATCH) { g_np[i] = 0u; g_cnt[i] = 0u; }
    if (i == 0) g_loss = 0.0;
}

__global__ __launch_bounds__(BT) void k_hist(const float4* __restrict__ pred,
                                             const int4* __restrict__ mask) {
    __shared__ unsigned sh[B1_BINS];
    __shared__ unsigned scnt;
    int b = blockIdx.y;
    for (int i = threadIdx.x; i < B1_BINS; i += BT) sh[i] = 0u;
    if (threadIdx.x == 0) scnt = 0u;
    __syncthreads();

    const float4* P = pred + (size_t)b * HW4;
    const int4*   M = mask + (size_t)b * HW4;
    unsigned localn = 0;
    for (unsigned v = blockIdx.x * BT + threadIdx.x; v < HW4; v += BT * GXH) {
        int4   m4 = M[v];
        float4 p4 = P[v];
        if (m4.x != 2) { localn++; atomicAdd(&sh[(score_key(p4.x, m4.x) >> 12) - B1_MIN], 1u); }
        if (m4.y != 2) { localn++; atomicAdd(&sh[(score_key(p4.y, m4.y) >> 12) - B1_MIN], 1u); }
        if (m4.z != 2) { localn++; atomicAdd(&sh[(score_key(p4.z, m4.z) >> 12) - B1_MIN], 1u); }
        if (m4.w != 2) { localn++; atomicAdd(&sh[(score_key(p4.w, m4.w) >> 12) - B1_MIN], 1u); }
    }
    atomicAdd(&scnt, localn);
    __syncthreads();
    for (int i = threadIdx.x; i < B1_BINS; i += BT) {
        unsigned v = sh[i];
        if (v) atomicAdd(&g_hist[b][i], v);
    }
    if (threadIdx.x == 0) atomicAdd(&g_np[b], scnt);
}

__global__ __launch_bounds__(1024) void k_select() {
    __shared__ unsigned s[1024];
    int b = blockIdx.x;
    int t = threadIdx.x;
    const int PB = 6;                 // 1024*6 >= 5249
    unsigned local = 0;
    #pragma unroll
    for (int j = 0; j < PB; j++) {
        int pos = t * PB + j;
        if (pos < B1_BINS) local += g_hist[b][B1_BINS - 1 - pos];  // descending
    }
    s[t] = local; __syncthreads();
    for (int off = 1; off < 1024; off <<= 1) {
        unsigned v = (t >= off) ? s[t - off] : 0u;
        __syncthreads();
        s[t] += v;
        __syncthreads();
    }
    unsigned before = s[t] - local;
    unsigned np  = g_np[b];
    unsigned ntr = (unsigned)(int)((float)np * 0.5f);  // matches (f32(n)*0.5).astype(i32)
    if (t == 0) g_ntr[b] = ntr;
    if (ntr == 0) {
        if (t == 0) { g_T[b] = 0xFFFFFFFFu; g_k1[b] = 0u; }
        return;
    }
    if (before < ntr && before + local >= ntr) {
        unsigned acc = before;
        for (int j = 0; j < PB; j++) {
            int pos = t * PB + j;
            if (pos >= B1_BINS) break;
            int bin = B1_BINS - 1 - pos;
            unsigned h = g_hist[b][bin];
            if (acc + h >= ntr) { g_T[b] = (unsigned)bin; g_k1[b] = ntr - acc; break; }
            acc += h;
        }
    }
}

__global__ __launch_bounds__(BT) void k_collect(const float4* __restrict__ pred,
                                                const int4* __restrict__ mask) {
    int b = blockIdx.y;
    unsigned T = g_T[b];
    if (T == 0xFFFFFFFFu) return;
    const float4* P = pred + (size_t)b * HW4;
    const int4*   M = mask + (size_t)b * HW4;
    for (unsigned v = blockIdx.x * BT + threadIdx.x; v < HW4; v += BT * GXC) {
        int4   m4 = M[v];
        float4 p4 = P[v];
        unsigned base = v * 4u;
        #pragma unroll
        for (int k = 0; k < 4; k++) {
            int   m = (k == 0) ? m4.x : (k == 1) ? m4.y : (k == 2) ? m4.z : m4.w;
            float p = (k == 0) ? p4.x : (k == 1) ? p4.y : (k == 2) ? p4.z : p4.w;
            if (m != 2) {
                unsigned key = score_key(p, m);
                if (((key >> 12) - B1_MIN) == T) {
                    unsigned pos = atomicAdd(&g_cnt[b], 1u);
                    if (pos < CAND_CAP) g_cand[b][pos] = make_uint2(key, base + k);
                }
            }
        }
    }
}

__global__ __launch_bounds__(256) void k_refine() {
    __shared__ unsigned h2[4096];
    __shared__ unsigned s[256];
    __shared__ unsigned eq[2048];
    __shared__ unsigned eqc;
    __shared__ unsigned shV, shKeq, shMeq;
    int b = blockIdx.x;
    int t = threadIdx.x;
    unsigned T = g_T[b];
    if (t == 0) {
        g_ic[b] = 0xFFFFFFFFu;                 // default: take all equals
        eqc = 0u; shV = 0xFFFFFFFFu; shKeq = 0u; shMeq = 0u;
        if (T != 0xFFFFFFFFu) g_V[b] = (T + B1_MIN) << 12;  // fallback (overwritten below)
        else                  g_V[b] = 0xFFFFFFFFu;         // select nothing
    }
    __syncthreads();
    if (T == 0xFFFFFFFFu) return;

    unsigned k1 = g_k1[b];
    unsigned nc = min(g_cnt[b], (unsigned)CAND_CAP);
    for (int i = t; i < 4096; i += 256) h2[i] = 0u;
    __syncthreads();
    for (unsigned i = t; i < nc; i += 256)
        atomicAdd(&h2[g_cand[b][i].x & 0xFFFu], 1u);
    __syncthreads();

    const int PB = 16;
    unsigned local = 0;
    #pragma unroll
    for (int j = 0; j < PB; j++) local += h2[4095 - (t * PB + j)];
    s[t] = local; __syncthreads();
    for (int off = 1; off < 256; off <<= 1) {
        unsigned v = (t >= off) ? s[t - off] : 0u;
        __syncthreads();
        s[t] += v;
        __syncthreads();
    }
    unsigned before = s[t] - local;
    if (before < k1 && before + local >= k1) {
        unsigned acc = before;
        for (int j = 0; j < PB; j++) {
            int v = 4095 - (t * PB + j);
            unsigned h = h2[v];
            if (acc + h >= k1) {
                unsigned V = ((T + B1_MIN) << 12) | (unsigned)v;
                shV = V; shKeq = k1 - acc; shMeq = h;
                g_V[b] = V;
                break;
            }
            acc += h;
        }
    }
    __syncthreads();
    unsigned V = shV, keq = shKeq, meq = shMeq;
    if (V == 0xFFFFFFFFu) return;            // degenerate fallback only
    if (keq == meq) return;                  // all equal-key elements selected

    for (unsigned i = t; i < nc; i += 256) {
        if (g_cand[b][i].x == V) {
            unsigned p = atomicAdd(&eqc, 1u);
            if (p < 2048u) eq[p] = g_cand[b][i].y;
        }
    }
    __syncthreads();
    unsigned m = min(eqc, 2048u);
    if (keq < m) {
        // find index with rank == keq (indices are distinct)
        for (unsigned i = t; i < m; i += 256) {
            unsigned x = eq[i], r = 0;
            for (unsigned j = 0; j < m; j++) r += (eq[j] < x) ? 1u : 0u;
            if (r == keq) g_ic[b] = x;       // select idx < g_ic
        }
    }
}

__global__ __launch_bounds__(BT) void k_final(const float4* __restrict__ pred,
                                              const int4* __restrict__ mask,
                                              float* __restrict__ out) {
    int b = blockIdx.y;
    unsigned V  = g_V[b];
    unsigned ic = g_ic[b];
    const float4* P = pred + (size_t)b * HW4;
    const int4*   M = mask + (size_t)b * HW4;
    // out+1 is only 4B-aligned -> scalar streaming stores for the masks
    float* outT = out + 1 + (size_t)b * HW;
    float* outH = out + 1 + (size_t)BATCH * HW + (size_t)b * HW;

    double acc = 0.0;
    for (unsigned v = blockIdx.x * BT + threadIdx.x; v < HW4; v += BT * GXF) {
        int4   m4 = M[v];
        float4 p4 = P[v];
        unsigned base = v * 4u;
        #pragma unroll
        for (int k = 0; k < 4; k++) {
            int   m = (k == 0) ? m4.x : (k == 1) ? m4.y : (k == 2) ? m4.z : m4.w;
            float p = (k == 0) ? p4.x : (k == 1) ? p4.y : (k == 2) ? p4.z : p4.w;
            bool ann = (m != 2);
            bool train = false;
            if (ann) {
                unsigned key = score_key(p, m);
                train = (key > V) || (key == V && (base + k) < ic);
            }
            bool hold = ann && !train;
            __stcs(&outT[base + k], train ? 1.0f : 0.0f);
            __stcs(&outH[base + k], hold  ? 1.0f : 0.0f);
            if (train) {
                float pc = fminf(fmaxf(p, 1e-7f), 1.0f - 1e-7f);
                float bce = (m == 1) ? -logf(pc) : -logf(1.0f - pc);
                acc += (double)bce;
            }
        }
    }
    // warp + block reduce, one double atomic per block
    #pragma unroll
    for (int off = 16; off; off >>= 1)
        acc += __shfl_down_sync(0xFFFFFFFFu, acc, off);
    __shared__ double w[BT / 32];
    int lane = threadIdx.x & 31, warp = threadIdx.x >> 5;
    if (lane == 0) w[warp] = acc;
    __syncthreads();
    if (threadIdx.x == 0) {
        double s2 = 0.0;
        #pragma unroll
        for (int i = 0; i < BT / 32; i++) s2 += w[i];
        atomicAdd(&g_loss, s2);
    }
}

__global__ void k_fin(float* __restrict__ out) {
    if (threadIdx.x == 0 && blockIdx.x == 0) {
        unsigned tot = 0;
        #pragma unroll
        for (int b = 0; b < BATCH; b++) tot += g_ntr[b];
        out[0] = (float)g_loss / ((float)tot + 1e-7f);
    }
}

extern "C" void kernel_launch(void* const* d_in, const int* in_sizes, int n_in,
                              void* d_out, int out_size) {
    const float4* pred = (const float4*)d_in[0];
    const int4*   mask = (const int4*)d_in[1];
    float* out = (float*)d_out;
    k_zero<<<128, 256>>>();
    k_hist<<<dim3(GXH, BATCH), BT>>>(pred, mask);
    k_select<<<BATCH, 1024>>>();
    k_collect<<<dim3(GXC, BATCH), BT>>>(pred, mask);
    k_refine<<<BATCH, 256>>>();
    k_final<<<dim3(GXF, BATCH), BT>>>(pred, mask, out);
    k_fin<<<1, 32>>>(out);
}